// round 12
// baseline (speedup 1.0000x reference)
#include <cuda_runtime.h>

// MoE conditional FFN: T=16, TOP_K=2, E=8, H=1024, I=2816, fp32.
// Expert-major grouping: each used expert's weights stream from HBM once.
//
// R8: phase2 = R7 skeleton (single-wave grid, rr loop, smem-staged h) with the
// pair loop made COMPILE-TIME 4 (padded) and fully interleaved:
//   4 independent accumulator chains (FMA lat hidden by 4-way ILP)
//   4 interleaved shfl butterflies (was: serial 130-cyc tail per pair)
//   weight row in 2 front-batched halves of 11 float4 (44 regs) -> ~95 regs,
//   2 blocks/SM preserved.
// R7's profile showed issue=18.8%/fma=7.5%/dram=34.7% => latency-chain bound
// in the non-unrolled runtime pair loop; this removes that chain.

#define NTOK   16
#define TOPK   2
#define NPAIR  (NTOK * TOPK)       // 32
#define HID    1024
#define INTER  2816
#define NEXP   8

__device__ float g_h[NPAIR * INTER];   // 360 KB scratch

__device__ __forceinline__ float dot4(float4 a, float4 b, float acc) {
    acc = fmaf(a.x, b.x, acc);
    acc = fmaf(a.y, b.y, acc);
    acc = fmaf(a.z, b.z, acc);
    return fmaf(a.w, b.w, acc);
}

// ---------------------------------------------------------------------------
// Phase 1 (R1's proven version, ~28.5us = 6.45 TB/s): untouched.
// ---------------------------------------------------------------------------
__global__ __launch_bounds__(256, 2)
void moe_phase1(const float* __restrict__ x,        // [T, H]
                const int*   __restrict__ eidx,     // [T, TOPK]
                const float* __restrict__ gate,     // [E, I, H]
                const float* __restrict__ down)     // [E, I, H]
{
    const int e = blockIdx.y;

    __shared__ int s_cnt;
    __shared__ int s_pair[NPAIR];
    if (threadIdx.x == 0) {
        int c = 0;
        #pragma unroll
        for (int i = 0; i < NPAIR; i++)
            if (eidx[i] == e) s_pair[c++] = i;
        s_cnt = c;
    }
    __syncthreads();
    const int cnt = s_cnt;
    if (cnt == 0) return;

    const int warp = threadIdx.x >> 5;
    const int lane = threadIdx.x & 31;
    const int row0 = blockIdx.x * 32 + warp * 4;

    const float4* gate4 = reinterpret_cast<const float4*>(gate + (size_t)e * INTER * HID);
    const float4* down4 = reinterpret_cast<const float4*>(down + (size_t)e * INTER * HID);

    for (int rr = 0; rr < 4; rr++) {
        const int row = row0 + rr;
        const float4* gr = gate4 + (size_t)row * (HID / 4);
        const float4* dr = down4 + (size_t)row * (HID / 4);

        float4 g4[8], d4[8];
        #pragma unroll
        for (int j = 0; j < 8; j++) {
            g4[j] = gr[lane + 32 * j];
            d4[j] = dr[lane + 32 * j];
        }

        for (int p = 0; p < cnt; p++) {
            const int pa = s_pair[p];
            const int t  = pa >> 1;
            const float4* xr = reinterpret_cast<const float4*>(x + (size_t)t * HID);

            float ag = 0.f, ad = 0.f;
            #pragma unroll
            for (int j = 0; j < 8; j++) {
                const float4 x4 = xr[lane + 32 * j];
                ag = dot4(g4[j], x4, ag);
                ad = dot4(d4[j], x4, ad);
            }
            #pragma unroll
            for (int off = 16; off; off >>= 1) {
                ag += __shfl_xor_sync(0xFFFFFFFFu, ag, off);
                ad += __shfl_xor_sync(0xFFFFFFFFu, ad, off);
            }
            if (lane == 0) {
                const float s = ag / (1.f + __expf(-ag));   // silu(gate)
                g_h[(size_t)pa * INTER + row] = s * ad;
            }
        }
    }
}

// ---------------------------------------------------------------------------
// Phase 2: out[pair,hh] = up[e,hh,:] . h[pair,:]
// grid = (HID/32, NEXP) = 256 blocks (single wave), block = 256 (8 warps).
// Pair list padded to a multiple of 4; chunk of exactly 4 pairs staged in smem;
// warp = 4 rows (rr loop); per row the weight is front-batched in 2 halves of
// 11 float4; the 4 pairs are consumed as 4 fully-interleaved acc chains and
// 4 interleaved shfl reductions.
// ---------------------------------------------------------------------------
#define CHUNK 4

__global__ __launch_bounds__(256, 2)
void moe_phase2(const int*   __restrict__ eidx,     // [T, TOPK]
                const float* __restrict__ up,       // [E, H, I]
                float*       __restrict__ out)      // [T, TOPK, H]
{
    const int e = blockIdx.y;

    __shared__ float s_h[CHUNK * INTER];            // 45056 B
    __shared__ int s_cnt4;
    __shared__ int s_pair[NPAIR + 3];

    const int tid = threadIdx.x;
    if (tid == 0) {
        int c = 0;
        #pragma unroll
        for (int i = 0; i < NPAIR; i++)
            if (eidx[i] == e) s_pair[c++] = i;
        int c4 = (c + 3) & ~3;                      // pad: duplicates of pair[0]
        for (int i = c; i < c4; i++) s_pair[i] = s_pair[0];
        s_cnt4 = (c == 0) ? 0 : c4;
    }
    __syncthreads();
    const int cnt4 = s_cnt4;
    if (cnt4 == 0) return;

    const int warp = tid >> 5;
    const int lane = tid & 31;
    const int row0 = blockIdx.x * 32 + warp * 4;

    const float4* up4 = reinterpret_cast<const float4*>(up + (size_t)e * HID * INTER);
    float4* s_h4 = reinterpret_cast<float4*>(s_h);

    for (int pb = 0; pb < cnt4; pb += CHUNK) {
        // Cooperative stage: 256 threads copy 4 h-rows from L2 (coalesced).
        __syncthreads();                            // previous chunk consumed
        for (int i = tid; i < CHUNK * (INTER / 4); i += 256) {
            const int pr = i / (INTER / 4);
            const int k  = i - pr * (INTER / 4);
            const float4* hr = reinterpret_cast<const float4*>(
                g_h + (size_t)s_pair[pb + pr] * INTER);
            s_h4[pr * (INTER / 4) + k] = hr[k];
        }
        __syncthreads();

        const int pa0 = s_pair[pb + 0], pa1 = s_pair[pb + 1];
        const int pa2 = s_pair[pb + 2], pa3 = s_pair[pb + 3];
        const float4* h0 = s_h4;
        const float4* h1 = s_h4 + 1 * (INTER / 4);
        const float4* h2 = s_h4 + 2 * (INTER / 4);
        const float4* h3 = s_h4 + 3 * (INTER / 4);

        for (int rr = 0; rr < 4; rr++) {
            const int row = row0 + rr;
            const float4* ur = up4 + (size_t)row * (INTER / 4);

            float a0 = 0.f, a1 = 0.f, a2 = 0.f, a3 = 0.f;

            #pragma unroll
            for (int half = 0; half < 2; half++) {
                float4 u[11];                       // front-batched half row
                #pragma unroll
                for (int j = 0; j < 11; j++)
                    u[j] = ur[lane + 32 * (11 * half + j)];

                #pragma unroll
                for (int j = 0; j < 11; j++) {
                    const int k = lane + 32 * (11 * half + j);
                    const float4 uj = u[j];
                    a0 = dot4(uj, h0[k], a0);       // 4 independent chains
                    a1 = dot4(uj, h1[k], a1);
                    a2 = dot4(uj, h2[k], a2);
                    a3 = dot4(uj, h3[k], a3);
                }
            }

            #pragma unroll
            for (int off = 16; off; off >>= 1) {    // 4 interleaved butterflies
                a0 += __shfl_xor_sync(0xFFFFFFFFu, a0, off);
                a1 += __shfl_xor_sync(0xFFFFFFFFu, a1, off);
                a2 += __shfl_xor_sync(0xFFFFFFFFu, a2, off);
                a3 += __shfl_xor_sync(0xFFFFFFFFu, a3, off);
            }
            if (lane == 0) {
                out[(size_t)pa0 * HID + row] = a0;  // dup pads rewrite same value
                out[(size_t)pa1 * HID + row] = a1;
                out[(size_t)pa2 * HID + row] = a2;
                out[(size_t)pa3 * HID + row] = a3;
            }
        }
    }
}

// ---------------------------------------------------------------------------
extern "C" void kernel_launch(void* const* d_in, const int* in_sizes, int n_in,
                              void* d_out, int out_size)
{
    const float* x    = (const float*)d_in[0];
    const int*   eidx = (const int*)  d_in[1];
    const float* gate = (const float*)d_in[2];
    const float* up   = (const float*)d_in[3];
    const float* down = (const float*)d_in[4];
    float* out = (float*)d_out;

    dim3 g1(INTER / 32, NEXP);   // 88 x 8
    moe_phase1<<<g1, 256>>>(x, eidx, gate, down);

    dim3 g2(HID / 32, NEXP);     // 32 x 8 = 256 blocks, single wave
    moe_phase2<<<g2, 256>>>(eidx, up, out);
}

// round 14
// speedup vs baseline: 1.0007x; 1.0007x over previous
#include <cuda_runtime.h>

// MoE conditional FFN: T=16, TOP_K=2, E=8, H=1024, I=2816, fp32.
// Expert-major grouping: each used expert's weights stream from HBM once.
//
// R9: R8's 4-pair interleave was right but spilled (regs hit the 128 cap,
// DRAM traffic 3x from local-memory spills). This version hand-schedules the
// weight row as a 3-section (8/8/6 float4) double-buffered pipeline using two
// 8-wide buffers -> peak ~100 live regs, no spill, 2 blocks/SM kept.
//   - 16 weight loads issued up front (MLP=16), sec0 computes under sec1/sec2
//   - 4 independent accumulator chains across the smem-staged pairs
//   - one interleaved 4-way butterfly per rr (R7 paid one per pair)

#define NTOK   16
#define TOPK   2
#define NPAIR  (NTOK * TOPK)       // 32
#define HID    1024
#define INTER  2816
#define NEXP   8

__device__ float g_h[NPAIR * INTER];   // 360 KB scratch

__device__ __forceinline__ float dot4(float4 a, float4 b, float acc) {
    acc = fmaf(a.x, b.x, acc);
    acc = fmaf(a.y, b.y, acc);
    acc = fmaf(a.z, b.z, acc);
    return fmaf(a.w, b.w, acc);
}

// ---------------------------------------------------------------------------
// Phase 1 (R1's proven version, ~5-6.5 TB/s): untouched.
// ---------------------------------------------------------------------------
__global__ __launch_bounds__(256, 2)
void moe_phase1(const float* __restrict__ x,        // [T, H]
                const int*   __restrict__ eidx,     // [T, TOPK]
                const float* __restrict__ gate,     // [E, I, H]
                const float* __restrict__ down)     // [E, I, H]
{
    const int e = blockIdx.y;

    __shared__ int s_cnt;
    __shared__ int s_pair[NPAIR];
    if (threadIdx.x == 0) {
        int c = 0;
        #pragma unroll
        for (int i = 0; i < NPAIR; i++)
            if (eidx[i] == e) s_pair[c++] = i;
        s_cnt = c;
    }
    __syncthreads();
    const int cnt = s_cnt;
    if (cnt == 0) return;

    const int warp = threadIdx.x >> 5;
    const int lane = threadIdx.x & 31;
    const int row0 = blockIdx.x * 32 + warp * 4;

    const float4* gate4 = reinterpret_cast<const float4*>(gate + (size_t)e * INTER * HID);
    const float4* down4 = reinterpret_cast<const float4*>(down + (size_t)e * INTER * HID);

    for (int rr = 0; rr < 4; rr++) {
        const int row = row0 + rr;
        const float4* gr = gate4 + (size_t)row * (HID / 4);
        const float4* dr = down4 + (size_t)row * (HID / 4);

        float4 g4[8], d4[8];
        #pragma unroll
        for (int j = 0; j < 8; j++) {
            g4[j] = gr[lane + 32 * j];
            d4[j] = dr[lane + 32 * j];
        }

        for (int p = 0; p < cnt; p++) {
            const int pa = s_pair[p];
            const int t  = pa >> 1;
            const float4* xr = reinterpret_cast<const float4*>(x + (size_t)t * HID);

            float ag = 0.f, ad = 0.f;
            #pragma unroll
            for (int j = 0; j < 8; j++) {
                const float4 x4 = xr[lane + 32 * j];
                ag = dot4(g4[j], x4, ag);
                ad = dot4(d4[j], x4, ad);
            }
            #pragma unroll
            for (int off = 16; off; off >>= 1) {
                ag += __shfl_xor_sync(0xFFFFFFFFu, ag, off);
                ad += __shfl_xor_sync(0xFFFFFFFFu, ad, off);
            }
            if (lane == 0) {
                const float s = ag / (1.f + __expf(-ag));   // silu(gate)
                g_h[(size_t)pa * INTER + row] = s * ad;
            }
        }
    }
}

// ---------------------------------------------------------------------------
// Phase 2: out[pair,hh] = up[e,hh,:] . h[pair,:]
// grid = (HID/32, NEXP) = 256 blocks (single wave), block = 256 (8 warps).
// Chunk of exactly 4 (padded) pairs staged in smem; warp = 4 rows (rr loop);
// per row: double-buffered 8/8/6 weight sections, 4 interleaved acc chains.
// ---------------------------------------------------------------------------
#define CHUNK 4

__global__ __launch_bounds__(256, 2)
void moe_phase2(const int*   __restrict__ eidx,     // [T, TOPK]
                const float* __restrict__ up,       // [E, H, I]
                float*       __restrict__ out)      // [T, TOPK, H]
{
    const int e = blockIdx.y;

    __shared__ float s_h[CHUNK * INTER];            // 45056 B
    __shared__ int s_cnt4;
    __shared__ int s_pair[NPAIR + 3];

    const int tid = threadIdx.x;
    if (tid == 0) {
        int c = 0;
        #pragma unroll
        for (int i = 0; i < NPAIR; i++)
            if (eidx[i] == e) s_pair[c++] = i;
        int c4 = (c + 3) & ~3;                      // pad: duplicates of pair[0]
        for (int i = c; i < c4; i++) s_pair[i] = s_pair[0];
        s_cnt4 = (c == 0) ? 0 : c4;
    }
    __syncthreads();
    const int cnt4 = s_cnt4;
    if (cnt4 == 0) return;

    const int warp = tid >> 5;
    const int lane = tid & 31;
    const int row0 = blockIdx.x * 32 + warp * 4;

    const float4* up4 = reinterpret_cast<const float4*>(up + (size_t)e * HID * INTER);
    float4* s_h4 = reinterpret_cast<float4*>(s_h);

    for (int pb = 0; pb < cnt4; pb += CHUNK) {
        // Cooperative stage: 256 threads copy 4 h-rows from L2 (coalesced).
        __syncthreads();                            // previous chunk consumed
        for (int i = tid; i < CHUNK * (INTER / 4); i += 256) {
            const int pr = i / (INTER / 4);
            const int k  = i - pr * (INTER / 4);
            const float4* hr = reinterpret_cast<const float4*>(
                g_h + (size_t)s_pair[pb + pr] * INTER);
            s_h4[pr * (INTER / 4) + k] = hr[k];
        }
        __syncthreads();

        const int pa0 = s_pair[pb + 0], pa1 = s_pair[pb + 1];
        const int pa2 = s_pair[pb + 2], pa3 = s_pair[pb + 3];
        const float4* h0 = s_h4;
        const float4* h1 = s_h4 + 1 * (INTER / 4);
        const float4* h2 = s_h4 + 2 * (INTER / 4);
        const float4* h3 = s_h4 + 3 * (INTER / 4);

        for (int rr = 0; rr < 4; rr++) {
            const int row = row0 + rr;
            const float4* ur = up4 + (size_t)row * (INTER / 4);

            float a0 = 0.f, a1 = 0.f, a2 = 0.f, a3 = 0.f;
            float4 ua[8], ub[8];

            // Front-issue sections 0 and 1 (16 loads in flight, MLP=16).
            #pragma unroll
            for (int j = 0; j < 8; j++) ua[j] = ur[lane + 32 * j];
            #pragma unroll
            for (int j = 0; j < 8; j++) ub[j] = ur[lane + 32 * (8 + j)];

            // Compute section 0 (4 independent chains).
            #pragma unroll
            for (int j = 0; j < 8; j++) {
                const int k = lane + 32 * j;
                const float4 uj = ua[j];
                a0 = dot4(uj, h0[k], a0);
                a1 = dot4(uj, h1[k], a1);
                a2 = dot4(uj, h2[k], a2);
                a3 = dot4(uj, h3[k], a3);
            }

            // Reload buffer A with section 2 (6 loads) behind section 1.
            #pragma unroll
            for (int j = 0; j < 6; j++) ua[j] = ur[lane + 32 * (16 + j)];

            // Compute section 1.
            #pragma unroll
            for (int j = 0; j < 8; j++) {
                const int k = lane + 32 * (8 + j);
                const float4 uj = ub[j];
                a0 = dot4(uj, h0[k], a0);
                a1 = dot4(uj, h1[k], a1);
                a2 = dot4(uj, h2[k], a2);
                a3 = dot4(uj, h3[k], a3);
            }

            // Compute section 2.
            #pragma unroll
            for (int j = 0; j < 6; j++) {
                const int k = lane + 32 * (16 + j);
                const float4 uj = ua[j];
                a0 = dot4(uj, h0[k], a0);
                a1 = dot4(uj, h1[k], a1);
                a2 = dot4(uj, h2[k], a2);
                a3 = dot4(uj, h3[k], a3);
            }

            #pragma unroll
            for (int off = 16; off; off >>= 1) {    // 4 interleaved butterflies
                a0 += __shfl_xor_sync(0xFFFFFFFFu, a0, off);
                a1 += __shfl_xor_sync(0xFFFFFFFFu, a1, off);
                a2 += __shfl_xor_sync(0xFFFFFFFFu, a2, off);
                a3 += __shfl_xor_sync(0xFFFFFFFFu, a3, off);
            }
            if (lane == 0) {
                out[(size_t)pa0 * HID + row] = a0;  // dup pads rewrite same value
                out[(size_t)pa1 * HID + row] = a1;
                out[(size_t)pa2 * HID + row] = a2;
                out[(size_t)pa3 * HID + row] = a3;
            }
        }
    }
}

// ---------------------------------------------------------------------------
extern "C" void kernel_launch(void* const* d_in, const int* in_sizes, int n_in,
                              void* d_out, int out_size)
{
    const float* x    = (const float*)d_in[0];
    const int*   eidx = (const int*)  d_in[1];
    const float* gate = (const float*)d_in[2];
    const float* up   = (const float*)d_in[3];
    const float* down = (const float*)d_in[4];
    float* out = (float*)d_out;

    dim3 g1(INTER / 32, NEXP);   // 88 x 8
    moe_phase1<<<g1, 256>>>(x, eidx, gate, down);

    dim3 g2(HID / 32, NEXP);     // 32 x 8 = 256 blocks, single wave
    moe_phase2<<<g2, 256>>>(eidx, up, out);
}